// round 14
// baseline (speedup 1.0000x reference)
#include <cuda_runtime.h>
#include <math.h>

// ---------------------------------------------------------------------------
// DOSAConLoss — single-launch, 16-block dedicated-pair-warp version
// (R13 config) + VECTOR-ATOMIC finalize:
//   * loc publish: ONE red.v2.f32 {accA,accB} from lane 0
//   * completion : ONE atom.acq_rel.add.v4.f32 {0,0,0,1} — bump returns the
//     prior {A,B,C,done} atomically, fusing the counter bump with the
//     accumulator read (removes one L2 round trip from the serial tail).
//
// loss_loc factorizes (reference broadcasts (N,1)/(N,) -> (N,N) mean):
//   loss_loc = (Sum_i dw_i*hw_i*(1-ciou_i)^2.5) * (Sum_j 1/(area_j+1e-7)) / N^2
//
// 16 blocks x 736 threads (23 warps):
//   warps 0-15 : loc, one box per thread (512 boxes/block, 8192 total)
//   warps 16-22: pair, one pair per warp (p = (w-16)*16 + blk, 112 >= 100)
//
// Memory-model note: each block's REDs happen-before its own release-RMW on
// the SAME 16B location (CTA barrier + release). RMW release sequences give
// the final acq_rel RMW visibility of all prior REDs in its return value.
// ---------------------------------------------------------------------------

#define EPSF        1e-7f
#define ALPHA_C     1.2f
#define TAU_C       0.3f
#define DELTA_C     1.0f
#define FOUR_PI2    0.40528473456935108577f   // 4/pi^2

#define TPB         736          // 23 warps: 16 loc + 7 pair
#define LOC_THREADS 512
#define PAIR_WARP0  16

struct __align__(16) Acc {
    float accA;            // Σ dw*hw*(1-ciou)^2.5
    float accB;            // Σ 1/(area+1e-7)
    float accC;            // Σ masked pair loss
    float doneF;           // block completion counter (float, +1.0 per block)
};
__device__ Acc g_acc = {0.0f, 0.0f, 0.0f, 0.0f};

// fused bump+read: atomically add {0,0,0,1} and return prior {A,B,C,done}
__device__ __forceinline__ float4 atom_add_v4_acqrel(Acc* p) {
    float4 prev;
    asm volatile(
        "atom.acq_rel.gpu.global.add.v4.f32 {%0,%1,%2,%3}, [%4], {%5,%6,%7,%8};"
        : "=f"(prev.x), "=f"(prev.y), "=f"(prev.z), "=f"(prev.w)
        : "l"(p), "f"(0.0f), "f"(0.0f), "f"(0.0f), "f"(1.0f)
        : "memory");
    return prev;
}

// fire-and-forget paired add of {a,b} to {accA,accB}
__device__ __forceinline__ void red_add_v2(float* p, float a, float b) {
    asm volatile("red.relaxed.gpu.global.add.v2.f32 [%0], {%1,%2};"
                 :: "l"(p), "f"(a), "f"(b) : "memory");
}

__device__ __forceinline__ void st_v4(Acc* p, float4 v) {
    asm volatile("st.global.v4.f32 [%0], {%1,%2,%3,%4};"
                 :: "l"(p), "f"(v.x), "f"(v.y), "f"(v.z), "f"(v.w)
                 : "memory");
}

// fast sqrt for strictly non-negative t (uses MUFU.RSQ)
__device__ __forceinline__ float fast_sqrt_nn(float t) {
    float tc = fmaxf(t, 1e-30f);
    return t * __frsqrt_rn(tc);
}

__global__ __launch_bounds__(TPB)
void dosa_split_kernel(const float4* __restrict__ pred,
                       const float4* __restrict__ tgt,
                       const float*  __restrict__ emb,
                       const float*  __restrict__ dens,
                       const int2*   __restrict__ idx,
                       float* __restrict__ out,
                       int N, int D, int P, int nblocks,
                       float invN2, float pairScale) {
    int lane = threadIdx.x & 31;
    int warp = threadIdx.x >> 5;

    if (warp >= PAIR_WARP0) {
        // ================= dedicated pair warps =================
        // Chain: idx -> (all gathers batched) -> fma -> shuffle -> RED.
        int p = (warp - PAIR_WARP0) * nblocks + blockIdx.x;
        if (p < P) {
            int2 ij = idx[p];
            int pi = ij.x, pj = ij.y;

            const float4* ei = (const float4*)(emb + (size_t)pi * D);
            const float4* ej = (const float4*)(emb + (size_t)pj * D);
            float4 bi = pred[pi];
            float4 bj = pred[pj];

            float s = 0.0f;
            if (D == 256) {
                // PEELED: issue all 4 loads before any dependent math.
                float4 u0 = ei[lane];
                float4 u1 = ei[lane + 32];
                float4 v0 = ej[lane];
                float4 v1 = ej[lane + 32];
                float d0 = u0.x - v0.x, d1 = u0.y - v0.y;
                float d2 = u0.z - v0.z, d3 = u0.w - v0.w;
                s = fmaf(d0, d0, s); s = fmaf(d1, d1, s);
                s = fmaf(d2, d2, s); s = fmaf(d3, d3, s);
                d0 = u1.x - v1.x; d1 = u1.y - v1.y;
                d2 = u1.z - v1.z; d3 = u1.w - v1.w;
                s = fmaf(d0, d0, s); s = fmaf(d1, d1, s);
                s = fmaf(d2, d2, s); s = fmaf(d3, d3, s);
            } else {
                int D4 = D >> 2;
                for (int c = lane; c < D4; c += 32) {
                    float4 u = ei[c];
                    float4 v = ej[c];
                    float d0 = u.x - v.x, d1 = u.y - v.y;
                    float d2 = u.z - v.z, d3 = u.w - v.w;
                    s = fmaf(d0, d0, s); s = fmaf(d1, d1, s);
                    s = fmaf(d2, d2, s); s = fmaf(d3, d3, s);
                }
            }
            #pragma unroll
            for (int off = 16; off > 0; off >>= 1)
                s += __shfl_down_sync(0xffffffffu, s, off);

            if (lane == 0) {
                float a_x1 = bi.x - bi.z * 0.5f, a_x2 = bi.x + bi.z * 0.5f;
                float a_y1 = bi.y - bi.w * 0.5f, a_y2 = bi.y + bi.w * 0.5f;
                float b_x1 = bj.x - bj.z * 0.5f, b_x2 = bj.x + bj.z * 0.5f;
                float b_y1 = bj.y - bj.w * 0.5f, b_y2 = bj.y + bj.w * 0.5f;
                float iw = fmaxf(fminf(a_x2, b_x2) - fmaxf(a_x1, b_x1), 0.0f);
                float ih = fmaxf(fminf(a_y2, b_y2) - fmaxf(a_y1, b_y1), 0.0f);
                float inter = iw * ih;
                float uni = bi.z * bi.w + bj.z * bj.w - inter + EPSF;
                float piou = __fdividef(inter, uni);
                if (piou > TAU_C) {
                    float d = fast_sqrt_nn(s);
                    float t = fmaxf(DELTA_C - d, 0.0f);
                    if (t > 0.0f) atomicAdd(&g_acc.accC, t * t);
                }
            }
        }
    } else {
        // ================= loc warps: one box per thread =================
        float accA = 0.0f, accB = 0.0f;
        int i = blockIdx.x * LOC_THREADS + threadIdx.x;
        if (i < N) {
            float4 b1 = pred[i];
            float4 b2 = tgt[i];
            float dv  = dens[i];

            float w1 = b1.z, h1 = b1.w, w2 = b2.z, h2 = b2.w;
            float b1x1 = b1.x - w1 * 0.5f, b1x2 = b1.x + w1 * 0.5f;
            float b1y1 = b1.y - h1 * 0.5f, b1y2 = b1.y + h1 * 0.5f;
            float b2x1 = b2.x - w2 * 0.5f, b2x2 = b2.x + w2 * 0.5f;
            float b2y1 = b2.y - h2 * 0.5f, b2y2 = b2.y + h2 * 0.5f;

            float iw = fmaxf(fminf(b1x2, b2x2) - fmaxf(b1x1, b2x1), 0.0f);
            float ih = fmaxf(fminf(b1y2, b2y2) - fmaxf(b1y1, b2y1), 0.0f);
            float inter = iw * ih;
            float uni   = w1 * h1 + w2 * h2 - inter + EPSF;
            float iou   = __fdividef(inter, uni);

            float cw = fmaxf(b1x2, b2x2) - fminf(b1x1, b2x1);
            float ch = fmaxf(b1y2, b2y2) - fminf(b1y1, b2y1);
            float c2 = cw * cw + ch * ch + EPSF;

            float dx = b2x1 + b2x2 - b1x1 - b1x2;
            float dy = b2y1 + b2y2 - b1y1 - b1y2;
            float rho2 = (dx * dx + dy * dy) * 0.25f;

            // atan(w2/h2) - atan(w1/h1) = atan((w2*h1 - w1*h2)/(h1*h2 + w1*w2))
            float num = w2 * h1 - w1 * h2;
            float den = fmaf(h1, h2, w1 * w2);
            float dat = atanf(__fdividef(num, den));
            float v   = FOUR_PI2 * dat * dat;
            float alpha = __fdividef(v, v - iou + (1.0f + EPSF));
            float ciou = iou - (__fdividef(rho2, c2) + v * alpha);

            float t  = 1.0f - ciou;                   // >= 0
            float pw = t * t * fast_sqrt_nn(t);       // t^2.5
            float dw = fmaf(ALPHA_C, dv, 1.0f);
            float hw = __fdividef(1.0f, 1.0f + __expf(fmaf(5.0f, ciou, -2.5f)));
            accA = dw * hw * pw;
            accB = __fdividef(1.0f, fmaf(w2, h2, 1e-7f));
        }
        #pragma unroll
        for (int off = 16; off > 0; off >>= 1) {
            accA += __shfl_down_sync(0xffffffffu, accA, off);
            accB += __shfl_down_sync(0xffffffffu, accB, off);
        }
        if (lane == 0)
            red_add_v2(&g_acc.accA, accA, accB);      // ONE vector RED
    }

    // ---- block completion: hb edge from all warps, then fused bump+read ----
    __syncthreads();
    if (threadIdx.x != 0) return;

    float4 prev = atom_add_v4_acqrel(&g_acc);   // returns prior {A,B,C,done}
    if (prev.w != (float)(nblocks - 1)) return; // not last block

    out[0] = prev.x * prev.y * invN2 + prev.z * pairScale;
    st_v4(&g_acc, make_float4(0.0f, 0.0f, 0.0f, 0.0f));  // reset for replay
}

extern "C" void kernel_launch(void* const* d_in, const int* in_sizes, int n_in,
                              void* d_out, int out_size) {
    const float4* pred = (const float4*)d_in[0];
    const float4* tgt  = (const float4*)d_in[1];
    const float*  emb  = (const float*)d_in[2];
    const float*  dens = (const float*)d_in[3];
    const int2*   idx  = (const int2*)d_in[4];
    float* out = (float*)d_out;

    int N = in_sizes[0] / 4;
    int D = in_sizes[2] / N;
    int P = in_sizes[4] / 2;

    int blocks = (N + LOC_THREADS - 1) / LOC_THREADS;     // 16
    int pairSlots = blocks * (TPB / 32 - PAIR_WARP0);     // 112
    if (pairSlots < P) blocks = (P + 6) / 7;              // safety (not hit)

    float invN2 = 1.0f / ((float)N * (float)N);
    float pairScale = 0.5f / ((float)P + 1e-7f);

    dosa_split_kernel<<<blocks, TPB>>>(pred, tgt, emb, dens, idx, out,
                                       N, D, P, blocks, invN2, pairScale);
}

// round 15
// speedup vs baseline: 1.0048x; 1.0048x over previous
#include <cuda_runtime.h>
#include <math.h>

// ---------------------------------------------------------------------------
// DOSAConLoss — single-launch, 16-block dedicated-pair-warp version
// (R14 config) + SPLIT BARRIER completion:
//   * warps 1-22: bar.arrive (non-blocking) -> retire immediately
//   * warp 0    : bar.sync   -> thread 0 fires the fused v4 bump+read
// Only one warp blocks at the barrier; the block tail drains faster.
//
// loss_loc factorizes (reference broadcasts (N,1)/(N,) -> (N,N) mean):
//   loss_loc = (Sum_i dw_i*hw_i*(1-ciou_i)^2.5) * (Sum_j 1/(area_j+1e-7)) / N^2
//
// 16 blocks x 736 threads (23 warps):
//   warps 0-15 : loc, one box per thread (512 boxes/block, 8192 total)
//   warps 16-22: pair, one pair per warp (p = (w-16)*16 + blk, 112 >= 100)
//
// Accumulators {A,B,C,done} in ONE 16B sector:
//   * loc publish : ONE red.relaxed.v2.f32 {accA,accB} (lane 0)
//   * pair publish: atomicAdd accC (lane 0, masked)
//   * completion  : ONE atom.acq_rel.add.v4.f32 {0,0,0,1} returning the
//     prior {A,B,C,done} — bump fused with accumulator read.
// ---------------------------------------------------------------------------

#define EPSF        1e-7f
#define ALPHA_C     1.2f
#define TAU_C       0.3f
#define DELTA_C     1.0f
#define FOUR_PI2    0.40528473456935108577f   // 4/pi^2

#define TPB         736          // 23 warps: 16 loc + 7 pair
#define LOC_THREADS 512
#define PAIR_WARP0  16

struct __align__(16) Acc {
    float accA;            // Σ dw*hw*(1-ciou)^2.5
    float accB;            // Σ 1/(area+1e-7)
    float accC;            // Σ masked pair loss
    float doneF;           // block completion counter (float, +1.0 per block)
};
__device__ Acc g_acc = {0.0f, 0.0f, 0.0f, 0.0f};

// fused bump+read: atomically add {0,0,0,1} and return prior {A,B,C,done}
__device__ __forceinline__ float4 atom_add_v4_acqrel(Acc* p) {
    float4 prev;
    asm volatile(
        "atom.acq_rel.gpu.global.add.v4.f32 {%0,%1,%2,%3}, [%4], {%5,%6,%7,%8};"
        : "=f"(prev.x), "=f"(prev.y), "=f"(prev.z), "=f"(prev.w)
        : "l"(p), "f"(0.0f), "f"(0.0f), "f"(0.0f), "f"(1.0f)
        : "memory");
    return prev;
}

// fire-and-forget paired add of {a,b} to {accA,accB}
__device__ __forceinline__ void red_add_v2(float* p, float a, float b) {
    asm volatile("red.relaxed.gpu.global.add.v2.f32 [%0], {%1,%2};"
                 :: "l"(p), "f"(a), "f"(b) : "memory");
}

__device__ __forceinline__ void st_v4(Acc* p, float4 v) {
    asm volatile("st.global.v4.f32 [%0], {%1,%2,%3,%4};"
                 :: "l"(p), "f"(v.x), "f"(v.y), "f"(v.z), "f"(v.w)
                 : "memory");
}

// fast sqrt for strictly non-negative t (uses MUFU.RSQ)
__device__ __forceinline__ float fast_sqrt_nn(float t) {
    float tc = fmaxf(t, 1e-30f);
    return t * __frsqrt_rn(tc);
}

__global__ __launch_bounds__(TPB)
void dosa_split_kernel(const float4* __restrict__ pred,
                       const float4* __restrict__ tgt,
                       const float*  __restrict__ emb,
                       const float*  __restrict__ dens,
                       const int2*   __restrict__ idx,
                       float* __restrict__ out,
                       int N, int D, int P, int nblocks,
                       float invN2, float pairScale) {
    int lane = threadIdx.x & 31;
    int warp = threadIdx.x >> 5;

    if (warp >= PAIR_WARP0) {
        // ================= dedicated pair warps =================
        // Chain: idx -> (all gathers batched) -> fma -> shuffle -> RED.
        int p = (warp - PAIR_WARP0) * nblocks + blockIdx.x;
        if (p < P) {
            int2 ij = idx[p];
            int pi = ij.x, pj = ij.y;

            const float4* ei = (const float4*)(emb + (size_t)pi * D);
            const float4* ej = (const float4*)(emb + (size_t)pj * D);
            float4 bi = pred[pi];
            float4 bj = pred[pj];

            float s = 0.0f;
            if (D == 256) {
                // PEELED: issue all 4 loads before any dependent math.
                float4 u0 = ei[lane];
                float4 u1 = ei[lane + 32];
                float4 v0 = ej[lane];
                float4 v1 = ej[lane + 32];
                float d0 = u0.x - v0.x, d1 = u0.y - v0.y;
                float d2 = u0.z - v0.z, d3 = u0.w - v0.w;
                s = fmaf(d0, d0, s); s = fmaf(d1, d1, s);
                s = fmaf(d2, d2, s); s = fmaf(d3, d3, s);
                d0 = u1.x - v1.x; d1 = u1.y - v1.y;
                d2 = u1.z - v1.z; d3 = u1.w - v1.w;
                s = fmaf(d0, d0, s); s = fmaf(d1, d1, s);
                s = fmaf(d2, d2, s); s = fmaf(d3, d3, s);
            } else {
                int D4 = D >> 2;
                for (int c = lane; c < D4; c += 32) {
                    float4 u = ei[c];
                    float4 v = ej[c];
                    float d0 = u.x - v.x, d1 = u.y - v.y;
                    float d2 = u.z - v.z, d3 = u.w - v.w;
                    s = fmaf(d0, d0, s); s = fmaf(d1, d1, s);
                    s = fmaf(d2, d2, s); s = fmaf(d3, d3, s);
                }
            }
            #pragma unroll
            for (int off = 16; off > 0; off >>= 1)
                s += __shfl_down_sync(0xffffffffu, s, off);

            if (lane == 0) {
                float a_x1 = bi.x - bi.z * 0.5f, a_x2 = bi.x + bi.z * 0.5f;
                float a_y1 = bi.y - bi.w * 0.5f, a_y2 = bi.y + bi.w * 0.5f;
                float b_x1 = bj.x - bj.z * 0.5f, b_x2 = bj.x + bj.z * 0.5f;
                float b_y1 = bj.y - bj.w * 0.5f, b_y2 = bj.y + bj.w * 0.5f;
                float iw = fmaxf(fminf(a_x2, b_x2) - fmaxf(a_x1, b_x1), 0.0f);
                float ih = fmaxf(fminf(a_y2, b_y2) - fmaxf(a_y1, b_y1), 0.0f);
                float inter = iw * ih;
                float uni = bi.z * bi.w + bj.z * bj.w - inter + EPSF;
                float piou = __fdividef(inter, uni);
                if (piou > TAU_C) {
                    float d = fast_sqrt_nn(s);
                    float t = fmaxf(DELTA_C - d, 0.0f);
                    if (t > 0.0f) atomicAdd(&g_acc.accC, t * t);
                }
            }
        }
    } else {
        // ================= loc warps: one box per thread =================
        float accA = 0.0f, accB = 0.0f;
        int i = blockIdx.x * LOC_THREADS + threadIdx.x;
        if (i < N) {
            float4 b1 = pred[i];
            float4 b2 = tgt[i];
            float dv  = dens[i];

            float w1 = b1.z, h1 = b1.w, w2 = b2.z, h2 = b2.w;
            float b1x1 = b1.x - w1 * 0.5f, b1x2 = b1.x + w1 * 0.5f;
            float b1y1 = b1.y - h1 * 0.5f, b1y2 = b1.y + h1 * 0.5f;
            float b2x1 = b2.x - w2 * 0.5f, b2x2 = b2.x + w2 * 0.5f;
            float b2y1 = b2.y - h2 * 0.5f, b2y2 = b2.y + h2 * 0.5f;

            float iw = fmaxf(fminf(b1x2, b2x2) - fmaxf(b1x1, b2x1), 0.0f);
            float ih = fmaxf(fminf(b1y2, b2y2) - fmaxf(b1y1, b2y1), 0.0f);
            float inter = iw * ih;
            float uni   = w1 * h1 + w2 * h2 - inter + EPSF;
            float iou   = __fdividef(inter, uni);

            float cw = fmaxf(b1x2, b2x2) - fminf(b1x1, b2x1);
            float ch = fmaxf(b1y2, b2y2) - fminf(b1y1, b2y1);
            float c2 = cw * cw + ch * ch + EPSF;

            float dx = b2x1 + b2x2 - b1x1 - b1x2;
            float dy = b2y1 + b2y2 - b1y1 - b1y2;
            float rho2 = (dx * dx + dy * dy) * 0.25f;

            // atan(w2/h2) - atan(w1/h1) = atan((w2*h1 - w1*h2)/(h1*h2 + w1*w2))
            float num = w2 * h1 - w1 * h2;
            float den = fmaf(h1, h2, w1 * w2);
            float dat = atanf(__fdividef(num, den));
            float v   = FOUR_PI2 * dat * dat;
            float alpha = __fdividef(v, v - iou + (1.0f + EPSF));
            float ciou = iou - (__fdividef(rho2, c2) + v * alpha);

            float t  = 1.0f - ciou;                   // >= 0
            float pw = t * t * fast_sqrt_nn(t);       // t^2.5
            float dw = fmaf(ALPHA_C, dv, 1.0f);
            float hw = __fdividef(1.0f, 1.0f + __expf(fmaf(5.0f, ciou, -2.5f)));
            accA = dw * hw * pw;
            accB = __fdividef(1.0f, fmaf(w2, h2, 1e-7f));
        }
        #pragma unroll
        for (int off = 16; off > 0; off >>= 1) {
            accA += __shfl_down_sync(0xffffffffu, accA, off);
            accB += __shfl_down_sync(0xffffffffu, accB, off);
        }
        if (lane == 0)
            red_add_v2(&g_acc.accA, accA, accB);      // ONE vector RED
    }

    // ---- split-barrier completion: only warp 0 blocks ----
    if (warp != 0) {
        // non-blocking arrive; warp retires immediately
        asm volatile("bar.arrive 1, %0;" :: "r"(TPB) : "memory");
        return;
    }
    asm volatile("bar.sync 1, %0;" :: "r"(TPB) : "memory");
    if (threadIdx.x != 0) return;

    float4 prev = atom_add_v4_acqrel(&g_acc);   // returns prior {A,B,C,done}
    if (prev.w != (float)(nblocks - 1)) return; // not last block

    out[0] = prev.x * prev.y * invN2 + prev.z * pairScale;
    st_v4(&g_acc, make_float4(0.0f, 0.0f, 0.0f, 0.0f));  // reset for replay
}

extern "C" void kernel_launch(void* const* d_in, const int* in_sizes, int n_in,
                              void* d_out, int out_size) {
    const float4* pred = (const float4*)d_in[0];
    const float4* tgt  = (const float4*)d_in[1];
    const float*  emb  = (const float*)d_in[2];
    const float*  dens = (const float*)d_in[3];
    const int2*   idx  = (const int2*)d_in[4];
    float* out = (float*)d_out;

    int N = in_sizes[0] / 4;
    int D = in_sizes[2] / N;
    int P = in_sizes[4] / 2;

    int blocks = (N + LOC_THREADS - 1) / LOC_THREADS;     // 16
    int pairSlots = blocks * (TPB / 32 - PAIR_WARP0);     // 112
    if (pairSlots < P) blocks = (P + 6) / 7;              // safety (not hit)

    float invN2 = 1.0f / ((float)N * (float)N);
    float pairScale = 0.5f / ((float)P + 1e-7f);

    dosa_split_kernel<<<blocks, TPB>>>(pred, tgt, emb, dens, idx, out,
                                       N, D, P, blocks, invN2, pairScale);
}